// round 11
// baseline (speedup 1.0000x reference)
#include <cuda_runtime.h>

// image2patch: input (256 imgs, 256, 256) f32 -> out (256, 3969, 64) f32.
// Patch grid 63x63 (stride 4, patch 8x8).
//
// Block = (img, patch-row-triple). 63 = 3*21, so each block handles prs
// {3bx, 3bx+1, 3bx+2}, which span 16 consecutive image rows (bands overlap
// 4 rows). Stage 16 rows x 64 float4 into smem with exactly 4x256 coalesced
// LDG.128 (no predication), then write 3*1008 = 3024 float4 -- one fully
// contiguous 48KB run -- with coalesced STG.128. Scatter lives in smem.
//
// smem row stride 66 float4: LDS.128 quarter-warp addr mod 8 =
// ((k4 mod 8) + pc) mod 8 -> 8 distinct bank-groups -> conflict-free.

#define N_PC        63
#define N_PATCHES   3969    // 63*63
#define ROW_F4      64      // 256 floats / 4
#define IMG_F4      16384   // 256*256 / 4
#define SROW        66      // smem row stride in float4 (padded)
#define OUT_F4      3024    // 3 * 63 patches * 16 float4

__global__ __launch_bounds__(256, 8)
void image2patch_kernel(const float4* __restrict__ in, float4* __restrict__ out) {
    __shared__ float4 s[16 * SROW];   // 16896 B

    const int tid = threadIdx.x;
    const int bx  = blockIdx.x;       // 0..20: triple of patch rows
    const int img = blockIdx.y;       // 0..255

    // ---- Load phase: 16 rows x 64 float4, coalesced, exactly 4 iters ----
    const float4* src = in + img * IMG_F4 + (bx * 12) * ROW_F4;
    #pragma unroll
    for (int i = 0; i < 4; i++) {
        const int idx = tid + i * 256;        // 0..1023
        const int row = idx >> 6;             // 0..15
        const int c4  = idx & 63;
        s[row * SROW + c4] = src[row * ROW_F4 + c4];
    }
    __syncthreads();

    // ---- Store phase: 3024 contiguous float4, coalesced ----
    float4* dst = out + (img * N_PATCHES + bx * 3 * N_PC) * 16;
    #pragma unroll
    for (int i = 0; i < 12; i++) {
        const int q = tid + i * 256;          // 0..3071
        if (q < OUT_F4) {
            const int p   = q >> 4;           // 0..188: patch within triple
            const int k4  = q & 15;           // float4 within patch
            const int prl = p / 63;           // 0..2: pr within triple (magic-mul)
            const int pc  = p - prl * 63;     // 0..62
            const int r   = prl * 4 + (k4 >> 1);   // staged row 0..15
            const int b   = k4 & 1;
            dst[q] = s[r * SROW + pc + b];
        }
    }
}

extern "C" void kernel_launch(void* const* d_in, const int* in_sizes, int n_in,
                              void* d_out, int out_size) {
    const float4* in  = (const float4*)d_in[0];
    float4*       out = (float4*)d_out;

    dim3 grid(21, 256, 1);    // (pr-triple, image)
    dim3 block(256, 1, 1);
    image2patch_kernel<<<grid, block>>>(in, out);
}

// round 12
// speedup vs baseline: 1.0066x; 1.0066x over previous
#include <cuda_runtime.h>

// image2patch: input (256 imgs, 256, 256) f32 -> out (256, 3969, 64) f32.
// Patch grid 63x63 (stride 4, patch 8x8).
//
// R8 structure (best so far): block = (img, patch_row). Stage the 8-row x
// 256-col band into smem with coalesced LDG.128, then emit the 63 patches
// (1008 contiguous float4) with coalesced STG.128. Scatter happens in smem.
//
// R12 delta: output stores use __stcs (evict-first streaming hint) so the
// 260 MB write stream drains L2 promptly instead of lazily, and input loads
// use __ldg. The kernel is DRAM-write-bound (in-window HBM traffic == the
// output stream); .cs targets the L2->DRAM writeback path directly.
//
// smem row stride 66 float4: LDS.128 quarter-warp addr mod 8 =
// (2r + pc + b) mod 8 -> all 8 bank-groups distinct -> conflict-free.

#define N_PC        63
#define N_PATCHES   3969    // 63*63
#define ROW_F4      64      // 256 floats / 4
#define IMG_F4      16384   // 256*256 / 4
#define SROW        66      // smem row stride in float4 (padded)
#define OUT_F4      1008    // 63 patches * 16 float4

__global__ __launch_bounds__(256, 8)
void image2patch_kernel(const float4* __restrict__ in, float4* __restrict__ out) {
    __shared__ float4 s[8 * SROW];   // 8448 B

    const int tid = threadIdx.x;
    const int pr  = blockIdx.x;      // 0..62
    const int img = blockIdx.y;      // 0..255

    // ---- Load phase: 8 rows x 64 float4, coalesced ----
    const float4* src = in + img * IMG_F4 + (pr * 4) * ROW_F4;
    {
        int idx = tid;                       // 0..255
        int row = idx >> 6, c4 = idx & 63;
        s[row * SROW + c4] = __ldg(&src[row * ROW_F4 + c4]);
        idx += 256;                          // 256..511
        row = idx >> 6; c4 = idx & 63;
        s[row * SROW + c4] = __ldg(&src[row * ROW_F4 + c4]);
    }
    __syncthreads();

    // ---- Store phase: 1008 contiguous float4, streaming stores ----
    float4* dst = out + (img * N_PATCHES + pr * N_PC) * 16;
    #pragma unroll
    for (int i = 0; i < 4; i++) {
        const int q = tid + i * 256;         // 0..1023
        if (q < OUT_F4) {
            const int pc = q >> 4;           // patch col 0..62
            const int k4 = q & 15;           // float4 within patch
            const int r  = k4 >> 1;          // row in band 0..7
            const int b  = k4 & 1;           // col half
            __stcs(&dst[q], s[r * SROW + pc + b]);
        }
    }
}

extern "C" void kernel_launch(void* const* d_in, const int* in_sizes, int n_in,
                              void* d_out, int out_size) {
    const float4* in  = (const float4*)d_in[0];
    float4*       out = (float4*)d_out;

    dim3 grid(63, 256, 1);    // (patch_row, image)
    dim3 block(256, 1, 1);
    image2patch_kernel<<<grid, block>>>(in, out);
}